// round 2
// baseline (speedup 1.0000x reference)
#include <cuda_runtime.h>
#include <stdint.h>

#define S 8192
#define D 4096
#define E 64
#define CAP 128

#define BT 32
#define KC 64
#define GEMM_THREADS 128

// output layout: [ l_aux (1) | combine (S*E*CAP) | dispatch (S*E*CAP) | exp_counts (E) ]
#define SEC ((size_t)S * E * CAP)
#define OFF_COMBINE ((size_t)1)
#define OFF_DISPATCH ((size_t)1 + SEC)
#define OFF_CNT ((size_t)1 + 2 * SEC)

// scratch (device globals: no allocation allowed)
__device__ float g_sel_gate[S];
__device__ int g_sel_idx[S];
__device__ int g_slots[S];
__device__ float g_me_sum[E];
__device__ int g_cnt[E];

__global__ void init_kernel() {
    int t = threadIdx.x;
    if (t < E) g_me_sum[t] = 0.f;
}

// ---------------------------------------------------------------------------
// Fused gate GEMM + softmax + argmax + per-expert gate-mean partial reduction.
// C[S,E] = x[S,D] @ w[E,D]^T, fp32. Block: 32 tokens x 64 experts, K-chunk 64.
// 128 threads, each computes a 4x4 register tile (4 tokens x 4 experts).
// ---------------------------------------------------------------------------
__global__ __launch_bounds__(GEMM_THREADS) void gate_gemm_kernel(
    const float* __restrict__ x, const float* __restrict__ w) {
    __shared__ float xs[BT][KC + 1];   // also reused for logits [BT][E]
    __shared__ float ws[E][KC + 1];
    __shared__ float s_max[BT];
    __shared__ float s_inv[BT];

    const int tid = threadIdx.x;
    const int tx = tid & 15;   // expert group (4 experts each)
    const int ty = tid >> 4;   // token group (4 tokens each)
    const int t0 = blockIdx.x * BT;

    float acc[4][4];
#pragma unroll
    for (int i = 0; i < 4; i++)
#pragma unroll
        for (int j = 0; j < 4; j++) acc[i][j] = 0.f;

    for (int kc = 0; kc < D; kc += KC) {
        // x tile: 32 rows x 64 cols = 512 float4, 4 per thread
#pragma unroll
        for (int l = 0; l < 4; l++) {
            int f4 = tid + l * GEMM_THREADS;
            int row = f4 >> 4;
            int c4 = f4 & 15;
            float4 v = *reinterpret_cast<const float4*>(
                &x[(size_t)(t0 + row) * D + kc + c4 * 4]);
            xs[row][c4 * 4 + 0] = v.x;
            xs[row][c4 * 4 + 1] = v.y;
            xs[row][c4 * 4 + 2] = v.z;
            xs[row][c4 * 4 + 3] = v.w;
        }
        // w tile: 64 rows x 64 cols = 1024 float4, 8 per thread
#pragma unroll
        for (int l = 0; l < 8; l++) {
            int f4 = tid + l * GEMM_THREADS;
            int row = f4 >> 4;
            int c4 = f4 & 15;
            float4 v = *reinterpret_cast<const float4*>(
                &w[(size_t)row * D + kc + c4 * 4]);
            ws[row][c4 * 4 + 0] = v.x;
            ws[row][c4 * 4 + 1] = v.y;
            ws[row][c4 * 4 + 2] = v.z;
            ws[row][c4 * 4 + 3] = v.w;
        }
        __syncthreads();
#pragma unroll
        for (int kk = 0; kk < KC; kk++) {
            float xv[4], wv[4];
#pragma unroll
            for (int i = 0; i < 4; i++) xv[i] = xs[4 * ty + i][kk];
#pragma unroll
            for (int j = 0; j < 4; j++) wv[j] = ws[4 * tx + j][kk];
#pragma unroll
            for (int i = 0; i < 4; i++)
#pragma unroll
                for (int j = 0; j < 4; j++) acc[i][j] += xv[i] * wv[j];
        }
        __syncthreads();
    }

    // logits -> smem (reuse xs: [32][65] holds [32][64])
#pragma unroll
    for (int i = 0; i < 4; i++)
#pragma unroll
        for (int j = 0; j < 4; j++) xs[4 * ty + i][4 * tx + j] = acc[i][j];
    __syncthreads();

    // per-token softmax + argmax (first-max tie-break like jnp.argmax)
    if (tid < BT) {
        const int t = tid;
        float m = xs[t][0];
        int am = 0;
#pragma unroll
        for (int e = 1; e < E; e++) {
            float v = xs[t][e];
            if (v > m) { m = v; am = e; }
        }
        float ssum = 0.f;
#pragma unroll
        for (int e = 0; e < E; e++) ssum += expf(xs[t][e] - m);
        float inv = 1.0f / ssum;
        s_max[t] = m;
        s_inv[t] = inv;
        g_sel_gate[t0 + t] = inv;  // gate at argmax = exp(0)/sum
        g_sel_idx[t0 + t] = am;
    }
    __syncthreads();

    // per-expert partial column sums of gates (for me / l_aux)
    if (tid < E) {
        const int e = tid;
        float cs = 0.f;
#pragma unroll
        for (int t = 0; t < BT; t++) cs += expf(xs[t][e] - s_max[t]) * s_inv[t];
        atomicAdd(&g_me_sum[e], cs);
    }
}

// ---------------------------------------------------------------------------
// Per-expert: count assigned, exact 128th-largest-noise threshold (bitwise
// binary search; fp32 in [0,1) so uint bit order == float order), then
// ordered block-scan to assign capacity slots.
// ---------------------------------------------------------------------------
#define BUF 5120
#define ETHREADS 256

__global__ __launch_bounds__(ETHREADS) void expert_kernel(
    const float* __restrict__ noise, float* __restrict__ out) {
    __shared__ uint32_t sbuf[BUF];
    __shared__ int scnt;
    __shared__ int sred;
    __shared__ int swsum[ETHREADS / 32];

    const int e = blockIdx.x;
    const int tid = threadIdx.x;
    const int lane = tid & 31;
    const int wid = tid >> 5;

    if (tid == 0) scnt = 0;
    __syncthreads();

    // gather assigned noises into smem (order irrelevant for threshold)
    for (int t = tid; t < S; t += ETHREADS) {
        if (g_sel_idx[t] == e) {
            int p = atomicAdd(&scnt, 1);
            if (p < BUF) sbuf[p] = __float_as_uint(noise[(size_t)t * E + e]);
        }
    }
    __syncthreads();
    const int cnt = scnt;
    if (tid == 0) {
        g_cnt[e] = cnt;
        out[OFF_CNT + e] = (float)cnt;
    }

    // threshold V = bits of the CAP-th largest noise (kept iff bits >= V)
    uint32_t V = 0;
    if (cnt > CAP) {
        const bool use_smem = (cnt <= BUF);
        for (int bit = 31; bit >= 0; bit--) {
            uint32_t trial = V | (1u << bit);
            int c = 0;
            if (use_smem) {
                for (int i = tid; i < cnt; i += ETHREADS)
                    c += (sbuf[i] >= trial) ? 1 : 0;
            } else {  // pathological skew fallback (never expected)
                for (int t = tid; t < S; t += ETHREADS)
                    c += (g_sel_idx[t] == e &&
                          __float_as_uint(noise[(size_t)t * E + e]) >= trial)
                             ? 1
                             : 0;
            }
#pragma unroll
            for (int off = 16; off; off >>= 1)
                c += __shfl_down_sync(0xffffffffu, c, off);
            __syncthreads();
            if (tid == 0) sred = 0;
            __syncthreads();
            if (lane == 0) atomicAdd(&sred, c);
            __syncthreads();
            if (sred >= CAP) V = trial;
        }
    }

    // ordered scan over tokens -> capacity slot (== per-expert cumsum - 1)
    int running = 0;
    for (int base = 0; base < S; base += ETHREADS) {
        int t = base + tid;
        bool assigned = (g_sel_idx[t] == e);
        bool kept = assigned &&
                    (__float_as_uint(noise[(size_t)t * E + e]) >= V);
        unsigned m = __ballot_sync(0xffffffffu, kept);
        int pre = __popc(m & ((1u << lane) - 1u));
        if (lane == 0) swsum[wid] = __popc(m);
        __syncthreads();
        int wbase = 0;
#pragma unroll
        for (int ww = 0; ww < ETHREADS / 32; ww++) {
            if (ww < wid) wbase += swsum[ww];
        }
        int tot = 0;
#pragma unroll
        for (int ww = 0; ww < ETHREADS / 32; ww++) tot += swsum[ww];
        if (assigned) g_slots[t] = kept ? (running + wbase + pre) : -1;
        running += tot;
        __syncthreads();
    }
}

// ---------------------------------------------------------------------------
// Finalize: scatter combine/dispatch nonzeros; compute l_aux.
// ---------------------------------------------------------------------------
__global__ __launch_bounds__(256) void finalize_kernel(float* __restrict__ out) {
    const int b = blockIdx.x;
    const int tid = threadIdx.x;
    if (b < S / 256) {
        int t = b * 256 + tid;
        int s = g_slots[t];
        if (s >= 0) {
            int e = g_sel_idx[t];
            size_t base = OFF_COMBINE + (((size_t)t * E + e) * CAP + (size_t)s);
            out[base] = g_sel_gate[t];
            out[base + SEC] = 1.0f;
        }
    } else {
        __shared__ float red[2];
        float v = 0.f;
        if (tid < E) v = g_me_sum[tid] * (float)g_cnt[tid];
#pragma unroll
        for (int off = 16; off; off >>= 1)
            v += __shfl_down_sync(0xffffffffu, v, off);
        if (tid == 0) red[0] = v;
        if (tid == 32) red[1] = v;
        __syncthreads();
        if (tid == 0)
            out[0] = (red[0] + red[1]) * ((float)E / ((float)S * (float)S));
    }
}

extern "C" void kernel_launch(void* const* d_in, const int* in_sizes, int n_in,
                              void* d_out, int out_size) {
    const float* x = (const float*)d_in[0];        // [S, D]
    const float* w = (const float*)d_in[1];        // [E, D]
    const float* noise = (const float*)d_in[2];    // [S, E]
    float* out = (float*)d_out;

    cudaMemsetAsync(d_out, 0, (size_t)out_size * sizeof(float), 0);
    init_kernel<<<1, 64>>>();
    gate_gemm_kernel<<<S / BT, GEMM_THREADS>>>(x, w);
    expert_kernel<<<E, ETHREADS>>>(noise, out);
    finalize_kernel<<<S / 256 + 1, 256>>>(out);
}